// round 15
// baseline (speedup 1.0000x reference)
#include <cuda_runtime.h>
#include <cstdint>

// ColorCurveLearningLoss: dual-path supply — TMA (cp.async.bulk) stages x into
// a 6-deep smem ring; p,t streamed via LDG.128 with register double-buffering.
// Splits traffic across the two independent SM request paths (TMA + L1tex LDG).
// mean_p - mean_t = sum(p-t)/cnt per (channel,bin) -> one packed 32-bit token
// per element: tok = 0x804000 + round(d*2^14)  (count bits [23,32), value [0,23))
// Overflow: <=29 stages * 4 = 116 elem/thread; value <= 116*2^15 = 3.8M < 2^23;
// count <= 116 < 512.
// Per-thread transposed smem histogram [bin][thread]: bank = tid mod 32 for
// any bin -> conflict-free RMW, no atomics.
// Grid: 9 x 48 chunks = 432 blocks @ 3 CTA/SM = one wave (24 warps/SM).
// Globals self-clean via atomicExch in last block.

#define NBINS 32
#define NSEG 96
#define BLOCK 256
#define NWARP (BLOCK / 32)
#define BLK_PER_CHUNK 9
#define NSTAGE 6
#define SGROUPS 256                      // float4 groups per stage (= BLOCK)
#define STAGE_BYTES (SGROUPS * 16)       // 4096 (x only)
#define MASK23 ((1u << 23) - 1u)

// dynamic smem layout
#define HIST_BYTES (NBINS * BLOCK * 4)           // 32768
#define RING_OFF   HIST_BYTES
#define RING_BYTES (NSTAGE * STAGE_BYTES)        // 24576
#define BAR_OFF    (RING_OFF + RING_BYTES)
#define SMEM_TOTAL (BAR_OFF + NSTAGE * 16)

__device__ unsigned long long g_q[NSEG];    // sum(p-t) * 2^14, two's complement
__device__ unsigned long long g_cnt[NSEG];
__device__ unsigned int g_done = 0;

__device__ __forceinline__ void mbar_init(uint32_t a, uint32_t cnt) {
    asm volatile("mbarrier.init.shared.b64 [%0], %1;" :: "r"(a), "r"(cnt) : "memory");
}
__device__ __forceinline__ void mbar_arrive(uint32_t a) {
    asm volatile("mbarrier.arrive.shared.b64 _, [%0];" :: "r"(a) : "memory");
}
__device__ __forceinline__ void mbar_expect_tx(uint32_t a, uint32_t bytes) {
    asm volatile("mbarrier.arrive.expect_tx.shared.b64 _, [%0], %1;"
                 :: "r"(a), "r"(bytes) : "memory");
}
__device__ __forceinline__ void mbar_wait(uint32_t a, uint32_t parity) {
    asm volatile(
        "{\n\t.reg .pred P;\n\t"
        "WAIT_%=:\n\t"
        "mbarrier.try_wait.parity.acquire.cta.shared::cta.b64 P, [%0], %1, 0x989680;\n\t"
        "@P bra.uni DONE_%=;\n\t"
        "bra.uni WAIT_%=;\n\t"
        "DONE_%=:\n\t}"
        :: "r"(a), "r"(parity) : "memory");
}
__device__ __forceinline__ void bulk_cp(uint32_t dst, const void* src,
                                        uint32_t bytes, uint32_t mbar) {
    asm volatile(
        "cp.async.bulk.shared::cta.global.mbarrier::complete_tx::bytes "
        "[%0], [%1], %2, [%3];"
        :: "r"(dst), "l"(src), "r"(bytes), "r"(mbar) : "memory");
}

__global__ void __launch_bounds__(BLOCK, 3) ccl_kernel(
    const float* __restrict__ pred,
    const float* __restrict__ target,
    const float* __restrict__ ximg,
    float* __restrict__ out,
    int groups_per_chunk,    // 65536
    int nblocks)
{
    extern __shared__ char smem[];
    uint32_t sbase;
    asm("{ .reg .u64 t; cvta.to.shared.u64 t, %1; cvt.u32.u64 %0, t; }"
        : "=r"(sbase) : "l"(smem));

    unsigned int* hist = (unsigned int*)smem;           // [NBINS][BLOCK]
    const int tid  = threadIdx.x;
    const int lane = tid & 31;
    const int warp = tid >> 5;
    const int chunk = blockIdx.y;                       // 0..47
    const int ch    = chunk % 3;

    const int gpb    = (groups_per_chunk + BLK_PER_CHUNK - 1) / BLK_PER_CHUNK;
    const int gstart = blockIdx.x * gpb;
    const int gcount = min(gpb, groups_per_chunk - gstart);
    const long long gbase = (long long)chunk * groups_per_chunk + gstart;
    const int nstages = (gcount + SGROUPS - 1) / SGROUPS;

    #pragma unroll
    for (int i = 0; i < NBINS; i++) hist[i * BLOCK + tid] = 0u;
    if (tid == 0) {
        #pragma unroll
        for (int s = 0; s < NSTAGE; s++) {
            mbar_init(sbase + BAR_OFF + s * 16, 1);         // full: tx-gated
            mbar_init(sbase + BAR_OFF + s * 16 + 8, NWARP); // empty: 1 per warp
        }
    }
    __syncthreads();

    // Pre-issue x for the first NSTAGE stages (x only: 4KB each).
    if (tid == 0) {
        for (int t = 0; t < NSTAGE && t < nstages; t++) {
            int sg  = t * SGROUPS;
            uint32_t bytes = (uint32_t)min(SGROUPS, gcount - sg) * 16u;
            uint32_t full  = sbase + BAR_OFF + t * 16;
            mbar_expect_tx(full, bytes);
            bulk_cp(sbase + RING_OFF + t * STAGE_BYTES,
                    ximg + 4ll * (gbase + sg), bytes, full);
        }
    }

    const float4* __restrict__ p4 = (const float4*)pred   + gbase;
    const float4* __restrict__ t4 = (const float4*)target + gbase;
    unsigned int* h = &hist[tid];        // h[b*BLOCK] == hist[b][tid]

    // Register double-buffer for p,t (LDG path).
    float4 pv, tv;
    if (tid < gcount) {
        pv = __ldg(p4 + tid);
        tv = __ldg(t4 + tid);
    }

    for (int s = 0; s < nstages; s++) {
        const int slot = s % NSTAGE;
        const uint32_t full  = sbase + BAR_OFF + slot * 16;
        const uint32_t empty = full + 8;
        const uint32_t par   = (uint32_t)((s / NSTAGE) & 1);

        // prefetch next stage's p,t while waiting for x
        int gn = (s + 1) * SGROUPS + tid;
        float4 pn, tn;
        bool vnext = gn < gcount;
        if (vnext) {
            pn = __ldg(p4 + gn);
            tn = __ldg(t4 + gn);
        }

        mbar_wait(full, par);

        int gcur = s * SGROUPS + tid;
        if (gcur < gcount) {
            float4 xv = *(const float4*)(smem + RING_OFF + slot * STAGE_BYTES
                                         + tid * 16);
            float xs[4] = { xv.x, xv.y, xv.z, xv.w };
            float ds[4] = { pv.x - tv.x, pv.y - tv.y, pv.z - tv.z, pv.w - tv.w };
            #pragma unroll
            for (int j = 0; j < 4; j++) {
                int b = (int)(xs[j] * 32.0f);          // exact floor(x*32)
                if ((unsigned)b < 32u) {
                    int q = __float2int_rn(ds[j] * 16384.0f);   // d * 2^14
                    h[b * BLOCK] += 0x804000u + (unsigned)q;
                }
            }
        }
        if (lane == 0) mbar_arrive(empty);
        pv = pn; tv = tn;

        // refill this x slot with stage s+NSTAGE once all warps arrived
        int t = s + NSTAGE;
        if (tid == 0 && t < nstages) {
            mbar_wait(empty, par);
            int sg2 = t * SGROUPS;
            uint32_t bytes = (uint32_t)min(SGROUPS, gcount - sg2) * 16u;
            mbar_expect_tx(full, bytes);
            bulk_cp(sbase + RING_OFF + slot * STAGE_BYTES,
                    ximg + 4ll * (gbase + sg2), bytes, full);
        }
    }
    __syncthreads();

    // Epilogue: warp w sweeps bins w, w+8, ...; lane reads column lane+32j
    // (conflict-free), shuffle-reduce, 2 global atomics per bin.
    for (int b = warp; b < NBINS; b += NWARP) {
        long long sumq = 0;
        long long cnt  = 0;
        #pragma unroll
        for (int j = 0; j < NWARP; j++) {
            unsigned int wd = hist[b * BLOCK + lane + 32 * j];
            unsigned int cc = wd >> 23;
            sumq += (long long)(wd & MASK23) - ((long long)cc << 14);
            cnt  += (long long)cc;
        }
        #pragma unroll
        for (int off = 16; off; off >>= 1) {
            sumq += __shfl_down_sync(0xffffffffu, sumq, off);
            cnt  += __shfl_down_sync(0xffffffffu, cnt,  off);
        }
        if (lane == 0 && cnt) {
            atomicAdd(&g_q[ch * NBINS + b], (unsigned long long)sumq);
            atomicAdd(&g_cnt[ch * NBINS + b], (unsigned long long)cnt);
        }
    }

    // Grid-done handshake; hist is dead -> reuse as scratch.
    __threadfence();
    __syncthreads();
    unsigned* lastflag = (unsigned*)&hist[0];
    double*   ws       = (double*)&hist[2 * BLOCK];
    if (tid == 0) {
        unsigned old = atomicAdd(&g_done, 1u);
        lastflag[0] = (old == (unsigned)(nblocks - 1)) ? 1u : 0u;
    }
    __syncthreads();
    if (lastflag[0]) {
        double v = 0.0;
        if (tid < NSEG) {
            unsigned long long cc = atomicExch(&g_cnt[tid], 0ull);  // read + reset
            long long qq = (long long)atomicExch(&g_q[tid], 0ull);
            if (cc) v = fabs((double)qq / ((double)cc * 16384.0));
        }
        #pragma unroll
        for (int off = 16; off; off >>= 1)
            v += __shfl_down_sync(0xffffffffu, v, off);
        if (lane == 0) ws[warp] = v;
        __syncthreads();
        if (tid == 0) {
            double tot = 0.0;
            #pragma unroll
            for (int w = 0; w < NWARP; w++) tot += ws[w];
            out[0] = (float)(tot / 96.0);
            atomicExch(&g_done, 0u);   // self-clean for next replay
        }
    }
}

extern "C" void kernel_launch(void* const* d_in, const int* in_sizes, int n_in,
                              void* d_out, int out_size) {
    const float* pred   = (const float*)d_in[0];
    const float* target = (const float*)d_in[1];
    const float* ximg   = (const float*)d_in[2];
    int n = in_sizes[0];                      // 16*3*512*512 = 12,582,912

    int groups_per_chunk = (n / 48) >> 2;     // 65536
    int nchunks = (n >> 2) / groups_per_chunk; // 48

    static int attr_set = 0;
    if (!attr_set) {
        cudaFuncSetAttribute(ccl_kernel,
                             cudaFuncAttributeMaxDynamicSharedMemorySize,
                             SMEM_TOTAL);
        attr_set = 1;
    }

    dim3 grid(BLK_PER_CHUNK, nchunks);        // 9 x 48 = 432 blocks
    ccl_kernel<<<grid, BLOCK, SMEM_TOTAL>>>(pred, target, ximg, (float*)d_out,
                                            groups_per_chunk,
                                            BLK_PER_CHUNK * nchunks);
}

// round 16
// speedup vs baseline: 1.1251x; 1.1251x over previous
#include <cuda_runtime.h>
#include <cstdint>

// ColorCurveLearningLoss: cp.async.bulk staged pipeline (8KB requests) +
// EARLY slot release + per-thread transposed smem histogram.
// mean_p - mean_t = sum(p-t)/cnt per (channel,bin) -> one packed 32-bit token
// per element: tok = 0x804000 + round(d*2^14)  (count bits [23,32), value [0,23))
// Overflow: <=171 elem/thread; value <= 171*2^15 = 5.6M < 2^23; count <= 171 < 512.
// Stage = 512 float4-groups: 3 x 8KB bulk copies (x,p,t). Consumers copy the
// stage to REGISTERS, arrive(empty) immediately (release semantics orders the
// LDS reads before the producer's refill), then run the bin/RMW math with the
// slot already recycling -> effective ring depth ~2x nominal.
// Per-thread transposed hist [bin][thread]: bank = tid mod 32, conflict-free.
// NSTAGE=3, hist 32KB + ring 72KB -> 2 CTA/SM; grid 6 x 48 = 288 = one wave;
// 144KB/SM guaranteed in flight. Globals self-clean via atomicExch.

#define NBINS 32
#define NSEG 96
#define BLOCK 256
#define NWARP (BLOCK / 32)
#define BLK_PER_CHUNK 6
#define NSTAGE 3
#define SGROUPS 512                      // float4 groups per stage (2 per thread)
#define STAGE_BYTES (SGROUPS * 16)       // 8192 per stream
#define MASK23 ((1u << 23) - 1u)

// dynamic smem layout
#define HIST_BYTES (NBINS * BLOCK * 4)           // 32768
#define RING_OFF   HIST_BYTES
#define RING_BYTES (NSTAGE * 3 * STAGE_BYTES)    // 73728
#define BAR_OFF    (RING_OFF + RING_BYTES)
#define SMEM_TOTAL (BAR_OFF + NSTAGE * 16)

__device__ unsigned long long g_q[NSEG];    // sum(p-t) * 2^14, two's complement
__device__ unsigned long long g_cnt[NSEG];
__device__ unsigned int g_done = 0;

__device__ __forceinline__ void mbar_init(uint32_t a, uint32_t cnt) {
    asm volatile("mbarrier.init.shared.b64 [%0], %1;" :: "r"(a), "r"(cnt) : "memory");
}
__device__ __forceinline__ void mbar_arrive(uint32_t a) {
    asm volatile("mbarrier.arrive.release.cta.shared::cta.b64 _, [%0];"
                 :: "r"(a) : "memory");
}
__device__ __forceinline__ void mbar_expect_tx(uint32_t a, uint32_t bytes) {
    asm volatile("mbarrier.arrive.expect_tx.shared.b64 _, [%0], %1;"
                 :: "r"(a), "r"(bytes) : "memory");
}
__device__ __forceinline__ void mbar_wait(uint32_t a, uint32_t parity) {
    asm volatile(
        "{\n\t.reg .pred P;\n\t"
        "WAIT_%=:\n\t"
        "mbarrier.try_wait.parity.acquire.cta.shared::cta.b64 P, [%0], %1, 0x989680;\n\t"
        "@P bra.uni DONE_%=;\n\t"
        "bra.uni WAIT_%=;\n\t"
        "DONE_%=:\n\t}"
        :: "r"(a), "r"(parity) : "memory");
}
__device__ __forceinline__ void bulk_cp(uint32_t dst, const void* src,
                                        uint32_t bytes, uint32_t mbar) {
    asm volatile(
        "cp.async.bulk.shared::cta.global.mbarrier::complete_tx::bytes "
        "[%0], [%1], %2, [%3];"
        :: "r"(dst), "l"(src), "r"(bytes), "r"(mbar) : "memory");
}

__global__ void __launch_bounds__(BLOCK, 2) ccl_kernel(
    const float* __restrict__ pred,
    const float* __restrict__ target,
    const float* __restrict__ ximg,
    float* __restrict__ out,
    int groups_per_chunk,    // 65536
    int nblocks)
{
    extern __shared__ char smem[];
    uint32_t sbase;
    asm("{ .reg .u64 t; cvta.to.shared.u64 t, %1; cvt.u32.u64 %0, t; }"
        : "=r"(sbase) : "l"(smem));

    unsigned int* hist = (unsigned int*)smem;           // [NBINS][BLOCK]
    const int tid  = threadIdx.x;
    const int lane = tid & 31;
    const int warp = tid >> 5;
    const int chunk = blockIdx.y;                       // 0..47
    const int ch    = chunk % 3;

    const int gpb    = (groups_per_chunk + BLK_PER_CHUNK - 1) / BLK_PER_CHUNK;
    const int gstart = blockIdx.x * gpb;
    const int gcount = min(gpb, groups_per_chunk - gstart);
    const long long ebase = ((long long)chunk * groups_per_chunk + gstart) * 4;
    const int nstages = (gcount + SGROUPS - 1) / SGROUPS;

    #pragma unroll
    for (int i = 0; i < NBINS; i++) hist[i * BLOCK + tid] = 0u;
    if (tid == 0) {
        #pragma unroll
        for (int s = 0; s < NSTAGE; s++) {
            mbar_init(sbase + BAR_OFF + s * 16, 1);         // full: tx-gated
            mbar_init(sbase + BAR_OFF + s * 16 + 8, NWARP); // empty: 1 per warp
        }
    }
    __syncthreads();

    // Pre-issue the first NSTAGE stages (3 x 8KB each).
    if (tid == 0) {
        for (int t = 0; t < NSTAGE && t < nstages; t++) {
            int sg  = t * SGROUPS;
            uint32_t bytes = (uint32_t)min(SGROUPS, gcount - sg) * 16u;
            uint32_t full  = sbase + BAR_OFF + t * 16;
            uint32_t dst   = sbase + RING_OFF + t * 3 * STAGE_BYTES;
            long long eo   = ebase + 4ll * sg;
            mbar_expect_tx(full, 3u * bytes);
            bulk_cp(dst,                   ximg   + eo, bytes, full);
            bulk_cp(dst + STAGE_BYTES,     pred   + eo, bytes, full);
            bulk_cp(dst + 2 * STAGE_BYTES, target + eo, bytes, full);
        }
    }

    unsigned int* h = &hist[tid];        // h[b*BLOCK] == hist[b][tid]

    for (int s = 0; s < nstages; s++) {
        const int slot = s % NSTAGE;
        const uint32_t full  = sbase + BAR_OFF + slot * 16;
        const uint32_t empty = full + 8;
        const uint32_t par   = (uint32_t)((s / NSTAGE) & 1);

        mbar_wait(full, par);

        // Copy this thread's 2 groups (x,p,t) to registers, then release slot.
        const char* stage = smem + RING_OFF + slot * 3 * STAGE_BYTES;
        int sg = s * SGROUPS;
        int g0 = sg + tid;
        int g1 = sg + BLOCK + tid;
        bool v0 = g0 < gcount, v1 = g1 < gcount;
        float4 xv0, pv0, tv0, xv1, pv1, tv1;
        if (v0) {
            xv0 = *(const float4*)(stage + tid * 16);
            pv0 = *(const float4*)(stage + STAGE_BYTES + tid * 16);
            tv0 = *(const float4*)(stage + 2 * STAGE_BYTES + tid * 16);
        }
        if (v1) {
            xv1 = *(const float4*)(stage + (BLOCK + tid) * 16);
            pv1 = *(const float4*)(stage + STAGE_BYTES + (BLOCK + tid) * 16);
            tv1 = *(const float4*)(stage + 2 * STAGE_BYTES + (BLOCK + tid) * 16);
        }
        if (lane == 0) mbar_arrive(empty);   // EARLY release: slot recycles now

        if (v0) {
            float xs[4] = { xv0.x, xv0.y, xv0.z, xv0.w };
            float ds[4] = { pv0.x - tv0.x, pv0.y - tv0.y, pv0.z - tv0.z, pv0.w - tv0.w };
            #pragma unroll
            for (int j = 0; j < 4; j++) {
                int b = (int)(xs[j] * 32.0f);          // exact floor(x*32)
                if ((unsigned)b < 32u) {
                    int q = __float2int_rn(ds[j] * 16384.0f);   // d * 2^14
                    h[b * BLOCK] += 0x804000u + (unsigned)q;
                }
            }
        }
        if (v1) {
            float xs[4] = { xv1.x, xv1.y, xv1.z, xv1.w };
            float ds[4] = { pv1.x - tv1.x, pv1.y - tv1.y, pv1.z - tv1.z, pv1.w - tv1.w };
            #pragma unroll
            for (int j = 0; j < 4; j++) {
                int b = (int)(xs[j] * 32.0f);
                if ((unsigned)b < 32u) {
                    int q = __float2int_rn(ds[j] * 16384.0f);
                    h[b * BLOCK] += 0x804000u + (unsigned)q;
                }
            }
        }

        // refill this slot with stage s+NSTAGE once all warps released it
        int t = s + NSTAGE;
        if (tid == 0 && t < nstages) {
            mbar_wait(empty, par);
            int sg2 = t * SGROUPS;
            uint32_t bytes = (uint32_t)min(SGROUPS, gcount - sg2) * 16u;
            uint32_t dst   = sbase + RING_OFF + slot * 3 * STAGE_BYTES;
            long long eo   = ebase + 4ll * sg2;
            mbar_expect_tx(full, 3u * bytes);
            bulk_cp(dst,                   ximg   + eo, bytes, full);
            bulk_cp(dst + STAGE_BYTES,     pred   + eo, bytes, full);
            bulk_cp(dst + 2 * STAGE_BYTES, target + eo, bytes, full);
        }
    }
    __syncthreads();

    // Epilogue: warp w sweeps bins w, w+8, ...; lane reads column lane+32j
    // (conflict-free), shuffle-reduce, 2 global atomics per bin.
    for (int b = warp; b < NBINS; b += NWARP) {
        long long sumq = 0;
        long long cnt  = 0;
        #pragma unroll
        for (int j = 0; j < NWARP; j++) {
            unsigned int wd = hist[b * BLOCK + lane + 32 * j];
            unsigned int cc = wd >> 23;
            sumq += (long long)(wd & MASK23) - ((long long)cc << 14);
            cnt  += (long long)cc;
        }
        #pragma unroll
        for (int off = 16; off; off >>= 1) {
            sumq += __shfl_down_sync(0xffffffffu, sumq, off);
            cnt  += __shfl_down_sync(0xffffffffu, cnt,  off);
        }
        if (lane == 0 && cnt) {
            atomicAdd(&g_q[ch * NBINS + b], (unsigned long long)sumq);
            atomicAdd(&g_cnt[ch * NBINS + b], (unsigned long long)cnt);
        }
    }

    // Grid-done handshake; hist is dead -> reuse as scratch.
    __threadfence();
    __syncthreads();
    unsigned* lastflag = (unsigned*)&hist[0];
    double*   ws       = (double*)&hist[2 * BLOCK];
    if (tid == 0) {
        unsigned old = atomicAdd(&g_done, 1u);
        lastflag[0] = (old == (unsigned)(nblocks - 1)) ? 1u : 0u;
    }
    __syncthreads();
    if (lastflag[0]) {
        double v = 0.0;
        if (tid < NSEG) {
            unsigned long long cc = atomicExch(&g_cnt[tid], 0ull);  // read + reset
            long long qq = (long long)atomicExch(&g_q[tid], 0ull);
            if (cc) v = fabs((double)qq / ((double)cc * 16384.0));
        }
        #pragma unroll
        for (int off = 16; off; off >>= 1)
            v += __shfl_down_sync(0xffffffffu, v, off);
        if (lane == 0) ws[warp] = v;
        __syncthreads();
        if (tid == 0) {
            double tot = 0.0;
            #pragma unroll
            for (int w = 0; w < NWARP; w++) tot += ws[w];
            out[0] = (float)(tot / 96.0);
            atomicExch(&g_done, 0u);   // self-clean for next replay
        }
    }
}

extern "C" void kernel_launch(void* const* d_in, const int* in_sizes, int n_in,
                              void* d_out, int out_size) {
    const float* pred   = (const float*)d_in[0];
    const float* target = (const float*)d_in[1];
    const float* ximg   = (const float*)d_in[2];
    int n = in_sizes[0];                      // 16*3*512*512 = 12,582,912

    int groups_per_chunk = (n / 48) >> 2;     // 65536
    int nchunks = (n >> 2) / groups_per_chunk; // 48

    static int attr_set = 0;
    if (!attr_set) {
        cudaFuncSetAttribute(ccl_kernel,
                             cudaFuncAttributeMaxDynamicSharedMemorySize,
                             SMEM_TOTAL);
        attr_set = 1;
    }

    dim3 grid(BLK_PER_CHUNK, nchunks);        // 6 x 48 = 288 blocks
    ccl_kernel<<<grid, BLOCK, SMEM_TOTAL>>>(pred, target, ximg, (float*)d_out,
                                            groups_per_chunk,
                                            BLK_PER_CHUNK * nchunks);
}